// round 4
// baseline (speedup 1.0000x reference)
#include <cuda_runtime.h>
#include <cuda_bf16.h>
#include <cstdint>

// ---------------- static scratch (no allocs allowed) ----------------
#define MAXN 10240
#define MAXE 330240
#define MAXW 320   // ceil(MAXN/32)

__device__ float   g_P[MAXN * 256];
__device__ float   g_Q[MAXN * 256];
__device__ float   g_nbr[MAXN * 256];
__device__ float   g_f2[MAXN * 256];
__device__ float   g_S1[MAXN * 256];
__device__ float   g_T1[MAXN * 256];
__device__ unsigned g_AB[MAXN * MAXW];
__device__ unsigned g_RB[MAXN * MAXW];
__device__ int     g_rowptr[MAXN + 1];
__device__ int     g_cursor[MAXN];
__device__ int     g_degcnt[MAXN];
__device__ int     g_csrcol[MAXE];
__device__ float   g_cnt2[MAXN];

// ---------------- zero scratch that accumulates ----------------
__global__ void zero_kernel(int n, int words) {
    size_t total = (size_t)n * words;
    for (size_t idx = (size_t)blockIdx.x * blockDim.x + threadIdx.x; idx < total;
         idx += (size_t)gridDim.x * blockDim.x) {
        g_AB[idx] = 0u;
        if (idx < (size_t)n) g_degcnt[idx] = 0;
    }
}

// ---------------- per-edge: degree count + adjacency bitset ----------------
__global__ void edge_prep_kernel(const int* __restrict__ row, const int* __restrict__ col,
                                 int E, int words) {
    int e = blockIdx.x * blockDim.x + threadIdx.x;
    if (e >= E) return;
    int r = row[e], c = col[e];
    atomicAdd(&g_degcnt[r], 1);
    atomicOr(&g_AB[(size_t)r * words + (c >> 5)], 1u << (c & 31));
}

// ---------------- exclusive scan (single CTA, chunked Kogge-Stone) ----------------
__global__ void scan_kernel(int n) {
    __shared__ int s[1024];
    __shared__ int carry_s;
    int t = threadIdx.x;
    if (t == 0) carry_s = 0;
    __syncthreads();
    for (int base = 0; base < n; base += 1024) {
        int v = (base + t < n) ? g_degcnt[base + t] : 0;
        s[t] = v;
        __syncthreads();
        for (int off = 1; off < 1024; off <<= 1) {
            int add = (t >= off) ? s[t - off] : 0;
            __syncthreads();
            s[t] += add;
            __syncthreads();
        }
        int excl = carry_s + s[t] - v;
        if (base + t < n) { g_rowptr[base + t] = excl; g_cursor[base + t] = excl; }
        __syncthreads();
        if (t == 1023) carry_s += s[1023];
        __syncthreads();
    }
    if (t == 0) g_rowptr[n] = carry_s;
}

// ---------------- CSR scatter ----------------
__global__ void scatter_kernel(const int* __restrict__ row, const int* __restrict__ col, int E) {
    int e = blockIdx.x * blockDim.x + threadIdx.x;
    if (e >= E) return;
    int r = row[e];
    int p = atomicAdd(&g_cursor[r], 1);
    g_csrcol[p] = col[e];
}

// ---------------- 1-hop: nbr_mean + 2-hop reach bitset + cnt2 ----------------
__global__ void hop1_kernel(const float* __restrict__ NT, int n, int words) {
    int i = blockIdx.x;
    int t = threadIdx.x;
    int t2 = 256 + t;
    int s0 = g_rowptr[i], s1 = g_rowptr[i + 1];
    unsigned w0 = 0u, w1 = 0u;
    float acc = 0.f;
    for (int p = s0; p < s1; p++) {
        int j = g_csrcol[p];
        const unsigned* abr = &g_AB[(size_t)j * words];
        if (t < words)  w0 |= abr[t];
        if (t2 < words) w1 |= abr[t2];
        acc += NT[(size_t)j * 256 + t];
    }
    int wi = i >> 5;
    unsigned sb = 1u << (i & 31);
    if (wi == t)  w0 &= ~sb;
    if (wi == t2) w1 &= ~sb;
    if (t < words)  g_RB[(size_t)i * words + t]  = w0;
    if (t2 < words) g_RB[(size_t)i * words + t2] = w1;

    int deg = s1 - s0;
    float inv = deg > 0 ? 1.f / (float)deg : 0.f;
    g_nbr[(size_t)i * 256 + t] = acc * inv;

    __shared__ int red[256];
    red[t] = __popc(w0) + __popc(w1);
    __syncthreads();
    for (int off = 128; off > 0; off >>= 1) {
        if (t < off) red[t] += red[t + off];
        __syncthreads();
    }
    if (t == 0) g_cnt2[i] = (float)red[0];
}

// ---------------- edge tokens: out2[e] = P[row[e]] + Q[col[e]] ----------------
__global__ void edge_tok_kernel(const int* __restrict__ row, const int* __restrict__ col,
                                float* __restrict__ out2, int E) {
    long long idx = (long long)blockIdx.x * blockDim.x + threadIdx.x;
    long long total = (long long)E * 64;
    if (idx >= total) return;
    int e = (int)(idx >> 6);
    int q = (int)(idx & 63);
    int r = row[e], c = col[e];
    float4 a = reinterpret_cast<const float4*>(g_P)[(size_t)r * 64 + q];
    float4 b = reinterpret_cast<const float4*>(g_Q)[(size_t)c * 64 + q];
    float4 o;
    o.x = a.x + b.x; o.y = a.y + b.y; o.z = a.z + b.z; o.w = a.w + b.w;
    reinterpret_cast<float4*>(out2)[idx] = o;
}

// ---------------- feat2 v2.1: smem-staged masks + float4 column ownership ----------------
#define F2_MI 68
#define F2_TR 192
#define F2_NG 17   // nodes per group (68/4)
__global__ __launch_bounds__(256, 1)
void feat2_kernel(const float* __restrict__ NT, int n, int words) {
    extern __shared__ float tile[];                      // F2_TR*256 floats
    unsigned* smask = (unsigned*)(tile + F2_TR * 256);   // F2_MI*6 words

    int t = threadIdx.x;
    int w = t >> 5;
    int l = t & 31;
    int g = w >> 1;          // node group 0..3
    int h = w & 1;           // column half
    int c0 = h * 128 + l * 4;
    int i0 = blockIdx.x * F2_MI;

    float acc[F2_NG][4];
#pragma unroll
    for (int k = 0; k < F2_NG; k++) {
        acc[k][0] = 0.f; acc[k][1] = 0.f; acc[k][2] = 0.f; acc[k][3] = 0.f;
    }

    int ntiles = (words + 5) / 6;
    for (int tb = 0; tb < ntiles; tb++) {
        int k0 = tb * F2_TR;
        for (int v = t; v < F2_TR * 64; v += 256) {
            int r = v >> 6;
            int c = (v & 63) << 2;
            int kk = k0 + r;
            float4 val = make_float4(0.f, 0.f, 0.f, 0.f);
            if (kk < n) val = *reinterpret_cast<const float4*>(&NT[(size_t)kk * 256 + c]);
            *reinterpret_cast<float4*>(&tile[r * 256 + c]) = val;
        }
        for (int v = t; v < F2_MI * 6; v += 256) {
            int m = v / 6, wl = v % 6;
            int i = i0 + m;
            int wd = tb * 6 + wl;
            smask[v] = (i < n && wd < words) ? g_RB[(size_t)i * words + wd] : 0u;
        }
        __syncthreads();
#pragma unroll
        for (int k = 0; k < F2_NG; k++) {
            int m = g * F2_NG + k;
#pragma unroll
            for (int wl = 0; wl < 6; wl++) {
                unsigned mask = smask[m * 6 + wl];
                while (mask) {
                    int b = __ffs(mask) - 1;
                    mask &= mask - 1;
                    const float4 v =
                        *reinterpret_cast<const float4*>(&tile[((wl << 5) + b) * 256 + c0]);
                    acc[k][0] += v.x; acc[k][1] += v.y;
                    acc[k][2] += v.z; acc[k][3] += v.w;
                }
            }
        }
        __syncthreads();
    }
#pragma unroll
    for (int k = 0; k < F2_NG; k++) {
        int i = i0 + g * F2_NG + k;
        if (i < n) {
            float c = g_cnt2[i];
            float inv = c > 0.f ? 1.f / c : 0.f;
            float4 o;
            o.x = acc[k][0] * inv; o.y = acc[k][1] * inv;
            o.z = acc[k][2] * inv; o.w = acc[k][3] * inv;
            *reinterpret_cast<float4*>(&g_f2[(size_t)i * 256 + c0]) = o;
        }
    }
}

// ---------------- SGEMM v3: 64x128 tile, 4x8 micro-tile, double-buffered ----------------
// C[M,256] = act( [A0|A1|A2][M,K] @ W[K,256] + bias )
// 256 threads, 3 CTAs/SM target (24 warps) for latency hiding.
__global__ __launch_bounds__(256, 3)
void sgemm_kernel(const float* __restrict__ A0, const float* __restrict__ A1,
                  const float* __restrict__ A2, int nblk,
                  const float* __restrict__ W, const float* __restrict__ bias,
                  float* __restrict__ C, int M, int relu) {
    __shared__ float As[2][16 * 68];    // [buf][BK][BM] transposed, padded 64->68
    __shared__ float Bs[2][16 * 128];   // [buf][BK][BN]
    int tid = threadIdx.x;
    int tx = tid & 15;       // col group: 8 cols tx*8..tx*8+7
    int ty = tid >> 4;       // row group: 4 rows ty*4..ty*4+3
    int row0 = blockIdx.y * 64;
    int col0 = blockIdx.x * 128;
    const float* Ab[3] = {A0, A1, A2};
    int K = nblk << 8;
    int ntiles = K >> 4;

    float acc[4][8];
#pragma unroll
    for (int i = 0; i < 4; i++)
#pragma unroll
        for (int j = 0; j < 8; j++) acc[i][j] = 0.f;

    // A load map: thread -> row ar (0..63), cols ac..ac+3
    int ar = tid >> 2;
    int ac = (tid & 3) << 2;
    // B load map: thread -> k-row br (0..15), cols bc..bc+7 (two float4)
    int br = tid >> 4;
    int bc = (tid & 15) << 3;

    int gar = row0 + ar;

    // ---- prologue: load tile 0 into buf 0 ----
    {
        const float* Ap = Ab[0];
        float4 av = make_float4(0.f, 0.f, 0.f, 0.f);
        if (gar < M) av = *reinterpret_cast<const float4*>(&Ap[(size_t)gar * 256 + ac]);
        As[0][(ac + 0) * 68 + ar] = av.x;
        As[0][(ac + 1) * 68 + ar] = av.y;
        As[0][(ac + 2) * 68 + ar] = av.z;
        As[0][(ac + 3) * 68 + ar] = av.w;
        float4 bv0 = *reinterpret_cast<const float4*>(&W[(size_t)br * 256 + col0 + bc]);
        float4 bv1 = *reinterpret_cast<const float4*>(&W[(size_t)br * 256 + col0 + bc + 4]);
        *reinterpret_cast<float4*>(&Bs[0][br * 128 + bc])     = bv0;
        *reinterpret_cast<float4*>(&Bs[0][br * 128 + bc + 4]) = bv1;
    }
    __syncthreads();

    int buf = 0;
    for (int t = 0; t < ntiles; t++) {
        // ---- prefetch next tile into registers (overlaps with compute) ----
        float4 av = make_float4(0.f, 0.f, 0.f, 0.f);
        float4 bv0, bv1;
        bool have_next = (t + 1 < ntiles);
        if (have_next) {
            int kt = (t + 1) << 4;
            const float* Ap = Ab[kt >> 8] + (kt & 255);
            if (gar < M) av = *reinterpret_cast<const float4*>(&Ap[(size_t)gar * 256 + ac]);
            bv0 = *reinterpret_cast<const float4*>(&W[(size_t)(kt + br) * 256 + col0 + bc]);
            bv1 = *reinterpret_cast<const float4*>(&W[(size_t)(kt + br) * 256 + col0 + bc + 4]);
        }

        // ---- compute on current buffer ----
        const float* Asb = As[buf];
        const float* Bsb = Bs[buf];
#pragma unroll
        for (int kk = 0; kk < 16; kk++) {
            float a[4], b[8];
            *reinterpret_cast<float4*>(&a[0]) =
                *reinterpret_cast<const float4*>(&Asb[kk * 68 + ty * 4]);
            *reinterpret_cast<float4*>(&b[0]) =
                *reinterpret_cast<const float4*>(&Bsb[kk * 128 + tx * 8]);
            *reinterpret_cast<float4*>(&b[4]) =
                *reinterpret_cast<const float4*>(&Bsb[kk * 128 + tx * 8 + 4]);
#pragma unroll
            for (int i = 0; i < 4; i++)
#pragma unroll
                for (int j = 0; j < 8; j++)
                    acc[i][j] += a[i] * b[j];
        }

        // ---- store prefetched regs into other buffer ----
        if (have_next) {
            int nb = buf ^ 1;
            As[nb][(ac + 0) * 68 + ar] = av.x;
            As[nb][(ac + 1) * 68 + ar] = av.y;
            As[nb][(ac + 2) * 68 + ar] = av.z;
            As[nb][(ac + 3) * 68 + ar] = av.w;
            *reinterpret_cast<float4*>(&Bs[nb][br * 128 + bc])     = bv0;
            *reinterpret_cast<float4*>(&Bs[nb][br * 128 + bc + 4]) = bv1;
        }
        __syncthreads();
        buf ^= 1;
    }

    float bv[8] = {0.f, 0.f, 0.f, 0.f, 0.f, 0.f, 0.f, 0.f};
    if (bias) {
        *reinterpret_cast<float4*>(&bv[0]) =
            *reinterpret_cast<const float4*>(&bias[col0 + tx * 8]);
        *reinterpret_cast<float4*>(&bv[4]) =
            *reinterpret_cast<const float4*>(&bias[col0 + tx * 8 + 4]);
    }
#pragma unroll
    for (int i = 0; i < 4; i++) {
        int row = row0 + ty * 4 + i;
        if (row < M) {
            float o[8];
#pragma unroll
            for (int j = 0; j < 8; j++) {
                float v = acc[i][j] + bv[j];
                if (relu) v = v > 0.f ? v : 0.f;
                o[j] = v;
            }
            *reinterpret_cast<float4*>(&C[(size_t)row * 256 + col0 + tx * 8]) =
                *reinterpret_cast<float4*>(&o[0]);
            *reinterpret_cast<float4*>(&C[(size_t)row * 256 + col0 + tx * 8 + 4]) =
                *reinterpret_cast<float4*>(&o[4]);
        }
    }
}

// ---------------- launch ----------------
extern "C" void kernel_launch(void* const* d_in, const int* in_sizes, int n_in,
                              void* d_out, int out_size) {
    const float* x    = (const float*)d_in[0];
    const int*   ei   = (const int*)d_in[1];
    const float* Wn   = (const float*)d_in[2];
    const float* bn   = (const float*)d_in[3];
    const float* We   = (const float*)d_in[4];
    const float* be   = (const float*)d_in[5];
    const float* Ws1  = (const float*)d_in[6];
    const float* bs1  = (const float*)d_in[7];
    const float* Ws2  = (const float*)d_in[8];
    const float* bs2  = (const float*)d_in[9];
    const float* Wh1  = (const float*)d_in[10];
    const float* bh1  = (const float*)d_in[11];
    const float* Wh2  = (const float*)d_in[12];
    const float* bh2  = (const float*)d_in[13];

    const int H = in_sizes[3];            // 256
    const int F = in_sizes[2] / H;        // 256
    const int N = in_sizes[0] / F;
    const int E = in_sizes[1] / 2;
    const int WORDS = (N + 31) / 32;
    (void)n_in; (void)out_size;

    const int* row = ei;
    const int* col = ei + E;

    float* out1 = (float*)d_out;                       // node_tokens
    float* out2 = out1 + (size_t)N * 256;              // edge_tokens
    float* out3 = out2 + (size_t)E * 256;              // subgraph_tokens
    float* out4 = out3 + (size_t)N * 256;              // neighborhood_tokens

    float *pP, *pQ, *pNbr, *pF2, *pS1, *pT1;
    cudaGetSymbolAddress((void**)&pP,  g_P);
    cudaGetSymbolAddress((void**)&pQ,  g_Q);
    cudaGetSymbolAddress((void**)&pNbr, g_nbr);
    cudaGetSymbolAddress((void**)&pF2, g_f2);
    cudaGetSymbolAddress((void**)&pS1, g_S1);
    cudaGetSymbolAddress((void**)&pT1, g_T1);

    size_t f2_smem = (size_t)(F2_TR * 256) * sizeof(float) + (F2_MI * 6) * sizeof(unsigned);
    cudaFuncSetAttribute(feat2_kernel, cudaFuncAttributeMaxDynamicSharedMemorySize,
                         (int)f2_smem);

    dim3 gblk(256);
    dim3 ggrid(2, (N + 63) / 64);   // 128-wide col tiles x 64-row tiles

    // zero accumulating scratch
    zero_kernel<<<512, 256>>>(N, WORDS);

    // tokenizer GEMMs: node_tokens -> out1, P = x@We_top + be, Q = x@We_bot
    sgemm_kernel<<<ggrid, gblk>>>(x, nullptr, nullptr, 1, Wn, bn, out1, N, 0);
    sgemm_kernel<<<ggrid, gblk>>>(x, nullptr, nullptr, 1, We, be, pP, N, 0);
    sgemm_kernel<<<ggrid, gblk>>>(x, nullptr, nullptr, 1, We + (size_t)F * 256, nullptr, pQ, N, 0);

    // graph structure
    int eb = (E + 255) / 256;
    edge_prep_kernel<<<eb, 256>>>(row, col, E, WORDS);
    scan_kernel<<<1, 1024>>>(N);
    scatter_kernel<<<eb, 256>>>(row, col, E);

    // 1-hop mean + 2-hop reach bitsets
    hop1_kernel<<<N, 256>>>(out1, N, WORDS);

    // edge tokens
    long long etot = (long long)E * 64;
    int etb = (int)((etot + 255) / 256);
    edge_tok_kernel<<<etb, 256>>>(row, col, out2, E);

    // feat2 (2-hop unique mean)
    int f2grid = (N + F2_MI - 1) / F2_MI;
    feat2_kernel<<<f2grid, 256, f2_smem>>>(out1, N, WORDS);

    // subgraph MLP
    sgemm_kernel<<<ggrid, gblk>>>(out1, pNbr, nullptr, 2, Ws1, bs1, pS1, N, 1);
    sgemm_kernel<<<ggrid, gblk>>>(pS1, nullptr, nullptr, 1, Ws2, bs2, out3, N, 0);

    // neighborhood MLP
    sgemm_kernel<<<ggrid, gblk>>>(out1, pNbr, pF2, 3, Wh1, bh1, pT1, N, 1);
    sgemm_kernel<<<ggrid, gblk>>>(pT1, nullptr, nullptr, 1, Wh2, bh2, out4, N, 0);
}

// round 5
// speedup vs baseline: 1.1123x; 1.1123x over previous
#include <cuda_runtime.h>
#include <cuda_bf16.h>
#include <cstdint>

// ---------------- static scratch (no allocs allowed) ----------------
#define MAXN 10240
#define MAXE 330240
#define MAXW 320   // ceil(MAXN/32)

__device__ float   g_P[MAXN * 256];
__device__ float   g_Q[MAXN * 256];
__device__ float   g_nbr[MAXN * 256];
__device__ float   g_f2[MAXN * 256];
__device__ float   g_S1[MAXN * 256];
__device__ float   g_T1[MAXN * 256];
__device__ unsigned g_AB[MAXN * MAXW];
__device__ unsigned g_RB[MAXN * MAXW];
__device__ int     g_rowptr[MAXN + 1];
__device__ int     g_cursor[MAXN];
__device__ int     g_degcnt[MAXN];
__device__ int     g_csrcol[MAXE];
__device__ float   g_cnt2[MAXN];

// ---------------- zero scratch that accumulates ----------------
__global__ void zero_kernel(int n, int words) {
    size_t total = (size_t)n * words;
    for (size_t idx = (size_t)blockIdx.x * blockDim.x + threadIdx.x; idx < total;
         idx += (size_t)gridDim.x * blockDim.x) {
        g_AB[idx] = 0u;
        if (idx < (size_t)n) g_degcnt[idx] = 0;
    }
}

// ---------------- per-edge: degree count + adjacency bitset ----------------
__global__ void edge_prep_kernel(const int* __restrict__ row, const int* __restrict__ col,
                                 int E, int words) {
    int e = blockIdx.x * blockDim.x + threadIdx.x;
    if (e >= E) return;
    int r = row[e], c = col[e];
    atomicAdd(&g_degcnt[r], 1);
    atomicOr(&g_AB[(size_t)r * words + (c >> 5)], 1u << (c & 31));
}

// ---------------- exclusive scan (single CTA, chunked Kogge-Stone) ----------------
__global__ void scan_kernel(int n) {
    __shared__ int s[1024];
    __shared__ int carry_s;
    int t = threadIdx.x;
    if (t == 0) carry_s = 0;
    __syncthreads();
    for (int base = 0; base < n; base += 1024) {
        int v = (base + t < n) ? g_degcnt[base + t] : 0;
        s[t] = v;
        __syncthreads();
        for (int off = 1; off < 1024; off <<= 1) {
            int add = (t >= off) ? s[t - off] : 0;
            __syncthreads();
            s[t] += add;
            __syncthreads();
        }
        int excl = carry_s + s[t] - v;
        if (base + t < n) { g_rowptr[base + t] = excl; g_cursor[base + t] = excl; }
        __syncthreads();
        if (t == 1023) carry_s += s[1023];
        __syncthreads();
    }
    if (t == 0) g_rowptr[n] = carry_s;
}

// ---------------- CSR scatter ----------------
__global__ void scatter_kernel(const int* __restrict__ row, const int* __restrict__ col, int E) {
    int e = blockIdx.x * blockDim.x + threadIdx.x;
    if (e >= E) return;
    int r = row[e];
    int p = atomicAdd(&g_cursor[r], 1);
    g_csrcol[p] = col[e];
}

// ---------------- 1-hop: nbr_mean + 2-hop reach bitset + cnt2 ----------------
__global__ void hop1_kernel(const float* __restrict__ NT, int n, int words) {
    int i = blockIdx.x;
    int t = threadIdx.x;
    int t2 = 256 + t;
    int s0 = g_rowptr[i], s1 = g_rowptr[i + 1];
    unsigned w0 = 0u, w1 = 0u;
    float acc = 0.f;
    for (int p = s0; p < s1; p++) {
        int j = g_csrcol[p];
        const unsigned* abr = &g_AB[(size_t)j * words];
        if (t < words)  w0 |= abr[t];
        if (t2 < words) w1 |= abr[t2];
        acc += NT[(size_t)j * 256 + t];
    }
    int wi = i >> 5;
    unsigned sb = 1u << (i & 31);
    if (wi == t)  w0 &= ~sb;
    if (wi == t2) w1 &= ~sb;
    if (t < words)  g_RB[(size_t)i * words + t]  = w0;
    if (t2 < words) g_RB[(size_t)i * words + t2] = w1;

    int deg = s1 - s0;
    float inv = deg > 0 ? 1.f / (float)deg : 0.f;
    g_nbr[(size_t)i * 256 + t] = acc * inv;

    __shared__ int red[256];
    red[t] = __popc(w0) + __popc(w1);
    __syncthreads();
    for (int off = 128; off > 0; off >>= 1) {
        if (t < off) red[t] += red[t + off];
        __syncthreads();
    }
    if (t == 0) g_cnt2[i] = (float)red[0];
}

// ---------------- edge tokens: out2[e] = P[row[e]] + Q[col[e]] ----------------
__global__ void edge_tok_kernel(const int* __restrict__ row, const int* __restrict__ col,
                                float* __restrict__ out2, int E) {
    long long idx = (long long)blockIdx.x * blockDim.x + threadIdx.x;
    long long total = (long long)E * 64;
    if (idx >= total) return;
    int e = (int)(idx >> 6);
    int q = (int)(idx & 63);
    int r = row[e], c = col[e];
    float4 a = reinterpret_cast<const float4*>(g_P)[(size_t)r * 64 + q];
    float4 b = reinterpret_cast<const float4*>(g_Q)[(size_t)c * 64 + q];
    float4 o;
    o.x = a.x + b.x; o.y = a.y + b.y; o.z = a.z + b.z; o.w = a.w + b.w;
    reinterpret_cast<float4*>(out2)[idx] = o;
}

// ---------------- feat2 v3: column-split, 64 nodes x 128 cols per CTA ----------------
// grid (ceil(n/64), 2). 2 CTAs/SM -> 4 warps/SMSP for latency hiding.
// Each warp owns 8 nodes; lane owns 4 columns (float4).
#define F2_MI 64
#define F2_TR 192
__global__ __launch_bounds__(256, 2)
void feat2_kernel(const float* __restrict__ NT, int n, int words) {
    extern __shared__ float tile[];                        // F2_TR*128 floats
    unsigned* smask = (unsigned*)(tile + F2_TR * 128);     // F2_MI*6 words

    int t = threadIdx.x;
    int w = t >> 5;
    int l = t & 31;
    int h = blockIdx.y;          // column half (0/1)
    int i0 = blockIdx.x * F2_MI;
    int cbase = h * 128 + l * 4;

    float acc[8][4];
#pragma unroll
    for (int k = 0; k < 8; k++) {
        acc[k][0] = 0.f; acc[k][1] = 0.f; acc[k][2] = 0.f; acc[k][3] = 0.f;
    }

    int ntiles = (words + 5) / 6;
    for (int tb = 0; tb < ntiles; tb++) {
        int k0 = tb * F2_TR;
        // tile load: 192 rows x 128 cols (this half)
        for (int v = t; v < F2_TR * 32; v += 256) {
            int r = v >> 5;
            int c = (v & 31) << 2;
            int kk = k0 + r;
            float4 val = make_float4(0.f, 0.f, 0.f, 0.f);
            if (kk < n)
                val = *reinterpret_cast<const float4*>(&NT[(size_t)kk * 256 + h * 128 + c]);
            *reinterpret_cast<float4*>(&tile[r * 128 + c]) = val;
        }
        // stage masks: 64 nodes x 6 words = 384 (strided)
        for (int v = t; v < F2_MI * 6; v += 256) {
            int m = v / 6, wl = v % 6;
            int i = i0 + m;
            int wd = tb * 6 + wl;
            smask[v] = (i < n && wd < words) ? g_RB[(size_t)i * words + wd] : 0u;
        }
        __syncthreads();
#pragma unroll
        for (int k = 0; k < 8; k++) {
            int m = w * 8 + k;
#pragma unroll
            for (int wl = 0; wl < 6; wl++) {
                unsigned mask = smask[m * 6 + wl];
                while (mask) {
                    int b = __ffs(mask) - 1;
                    mask &= mask - 1;
                    const float4 v =
                        *reinterpret_cast<const float4*>(&tile[((wl << 5) + b) * 128 + l * 4]);
                    acc[k][0] += v.x; acc[k][1] += v.y;
                    acc[k][2] += v.z; acc[k][3] += v.w;
                }
            }
        }
        __syncthreads();
    }
#pragma unroll
    for (int k = 0; k < 8; k++) {
        int i = i0 + w * 8 + k;
        if (i < n) {
            float c = g_cnt2[i];
            float inv = c > 0.f ? 1.f / c : 0.f;
            float4 o;
            o.x = acc[k][0] * inv; o.y = acc[k][1] * inv;
            o.z = acc[k][2] * inv; o.w = acc[k][3] * inv;
            *reinterpret_cast<float4*>(&g_f2[(size_t)i * 256 + cbase]) = o;
        }
    }
}

// ---------------- SGEMM v5: 128x128 tile, 8x8 micro, double-buffered, job-fused ----------------
struct Job {
    const float* A0; const float* A1; const float* A2;
    const float* W;  const float* b;  float* C;
    int nblk; int relu;
};

__global__ __launch_bounds__(256)
void sgemm_kernel(Job j0, Job j1, Job j2, int M) {
    __shared__ float As[2][16 * 132];   // [buf][BK][BM] transposed, padded
    __shared__ float Bs[2][16 * 128];   // [buf][BK][BN]

    int z = blockIdx.z;
    Job jb = (z == 0) ? j0 : ((z == 1) ? j1 : j2);
    const float* A0 = jb.A0;
    const float* A1 = jb.A1;
    const float* A2 = jb.A2;
    const float* W  = jb.W;
    const float* bias = jb.b;
    float* C = jb.C;
    int nblk = jb.nblk;
    int relu = jb.relu;

    int tid = threadIdx.x;
    int tx = tid & 15;
    int ty = tid >> 4;
    int row0 = blockIdx.y * 128;
    int col0 = blockIdx.x * 128;
    int ntiles = nblk << 4;   // (nblk*256)/16

    float acc[8][8];
#pragma unroll
    for (int i = 0; i < 8; i++)
#pragma unroll
        for (int j = 0; j < 8; j++) acc[i][j] = 0.f;

    int ar = tid >> 2;          // 0..63
    int ac = (tid & 3) << 2;    // 0,4,8,12
    int br = tid >> 5;          // 0..7
    int bc = (tid & 31) << 2;   // 0..124

    int gr0 = row0 + ar;
    int gr1 = row0 + ar + 64;

    // ---- prologue: tile 0 -> buf 0 ----
    {
        const float* Ap = A0;
        float4 a0 = make_float4(0.f, 0.f, 0.f, 0.f);
        float4 a1 = make_float4(0.f, 0.f, 0.f, 0.f);
        if (gr0 < M) a0 = *reinterpret_cast<const float4*>(&Ap[(size_t)gr0 * 256 + ac]);
        if (gr1 < M) a1 = *reinterpret_cast<const float4*>(&Ap[(size_t)gr1 * 256 + ac]);
        As[0][(ac + 0) * 132 + ar] = a0.x;
        As[0][(ac + 1) * 132 + ar] = a0.y;
        As[0][(ac + 2) * 132 + ar] = a0.z;
        As[0][(ac + 3) * 132 + ar] = a0.w;
        As[0][(ac + 0) * 132 + ar + 64] = a1.x;
        As[0][(ac + 1) * 132 + ar + 64] = a1.y;
        As[0][(ac + 2) * 132 + ar + 64] = a1.z;
        As[0][(ac + 3) * 132 + ar + 64] = a1.w;
        float4 b0 = *reinterpret_cast<const float4*>(&W[(size_t)br * 256 + col0 + bc]);
        float4 b1 = *reinterpret_cast<const float4*>(&W[(size_t)(br + 8) * 256 + col0 + bc]);
        *reinterpret_cast<float4*>(&Bs[0][br * 128 + bc])       = b0;
        *reinterpret_cast<float4*>(&Bs[0][(br + 8) * 128 + bc]) = b1;
    }
    __syncthreads();

    int buf = 0;
    for (int t = 0; t < ntiles; t++) {
        bool have_next = (t + 1 < ntiles);
        float4 a0 = make_float4(0.f, 0.f, 0.f, 0.f);
        float4 a1 = make_float4(0.f, 0.f, 0.f, 0.f);
        float4 b0, b1;
        if (have_next) {
            int kt = (t + 1) << 4;
            const float* Ap = (kt < 256) ? A0 : ((kt < 512) ? A1 : A2);
            int ko = kt & 255;
            if (gr0 < M) a0 = *reinterpret_cast<const float4*>(&Ap[(size_t)gr0 * 256 + ko + ac]);
            if (gr1 < M) a1 = *reinterpret_cast<const float4*>(&Ap[(size_t)gr1 * 256 + ko + ac]);
            b0 = *reinterpret_cast<const float4*>(&W[(size_t)(kt + br) * 256 + col0 + bc]);
            b1 = *reinterpret_cast<const float4*>(&W[(size_t)(kt + br + 8) * 256 + col0 + bc]);
        }

        const float* Asb = As[buf];
        const float* Bsb = Bs[buf];
#pragma unroll
        for (int kk = 0; kk < 16; kk++) {
            float a[8], b[8];
            *reinterpret_cast<float4*>(&a[0]) =
                *reinterpret_cast<const float4*>(&Asb[kk * 132 + ty * 4]);
            *reinterpret_cast<float4*>(&a[4]) =
                *reinterpret_cast<const float4*>(&Asb[kk * 132 + 64 + ty * 4]);
            *reinterpret_cast<float4*>(&b[0]) =
                *reinterpret_cast<const float4*>(&Bsb[kk * 128 + tx * 4]);
            *reinterpret_cast<float4*>(&b[4]) =
                *reinterpret_cast<const float4*>(&Bsb[kk * 128 + 64 + tx * 4]);
#pragma unroll
            for (int i = 0; i < 8; i++)
#pragma unroll
                for (int j = 0; j < 8; j++)
                    acc[i][j] += a[i] * b[j];
        }

        if (have_next) {
            int nb = buf ^ 1;
            As[nb][(ac + 0) * 132 + ar] = a0.x;
            As[nb][(ac + 1) * 132 + ar] = a0.y;
            As[nb][(ac + 2) * 132 + ar] = a0.z;
            As[nb][(ac + 3) * 132 + ar] = a0.w;
            As[nb][(ac + 0) * 132 + ar + 64] = a1.x;
            As[nb][(ac + 1) * 132 + ar + 64] = a1.y;
            As[nb][(ac + 2) * 132 + ar + 64] = a1.z;
            As[nb][(ac + 3) * 132 + ar + 64] = a1.w;
            *reinterpret_cast<float4*>(&Bs[nb][br * 128 + bc])       = b0;
            *reinterpret_cast<float4*>(&Bs[nb][(br + 8) * 128 + bc]) = b1;
        }
        __syncthreads();
        buf ^= 1;
    }

    float bv[8] = {0.f, 0.f, 0.f, 0.f, 0.f, 0.f, 0.f, 0.f};
    if (bias) {
        *reinterpret_cast<float4*>(&bv[0]) =
            *reinterpret_cast<const float4*>(&bias[col0 + tx * 4]);
        *reinterpret_cast<float4*>(&bv[4]) =
            *reinterpret_cast<const float4*>(&bias[col0 + 64 + tx * 4]);
    }
#pragma unroll
    for (int gi = 0; gi < 2; gi++) {
#pragma unroll
        for (int i = 0; i < 4; i++) {
            int row = row0 + gi * 64 + ty * 4 + i;
            if (row < M) {
#pragma unroll
                for (int gj = 0; gj < 2; gj++) {
                    float o[4];
#pragma unroll
                    for (int j = 0; j < 4; j++) {
                        float v = acc[gi * 4 + i][gj * 4 + j] + bv[gj * 4 + j];
                        if (relu) v = v > 0.f ? v : 0.f;
                        o[j] = v;
                    }
                    *reinterpret_cast<float4*>(&C[(size_t)row * 256 + col0 + gj * 64 + tx * 4]) =
                        *reinterpret_cast<float4*>(o);
                }
            }
        }
    }
}

// ---------------- launch ----------------
extern "C" void kernel_launch(void* const* d_in, const int* in_sizes, int n_in,
                              void* d_out, int out_size) {
    const float* x    = (const float*)d_in[0];
    const int*   ei   = (const int*)d_in[1];
    const float* Wn   = (const float*)d_in[2];
    const float* bn   = (const float*)d_in[3];
    const float* We   = (const float*)d_in[4];
    const float* be   = (const float*)d_in[5];
    const float* Ws1  = (const float*)d_in[6];
    const float* bs1  = (const float*)d_in[7];
    const float* Ws2  = (const float*)d_in[8];
    const float* bs2  = (const float*)d_in[9];
    const float* Wh1  = (const float*)d_in[10];
    const float* bh1  = (const float*)d_in[11];
    const float* Wh2  = (const float*)d_in[12];
    const float* bh2  = (const float*)d_in[13];

    const int H = in_sizes[3];            // 256
    const int F = in_sizes[2] / H;        // 256
    const int N = in_sizes[0] / F;
    const int E = in_sizes[1] / 2;
    const int WORDS = (N + 31) / 32;
    (void)n_in; (void)out_size;

    const int* row = ei;
    const int* col = ei + E;

    float* out1 = (float*)d_out;                       // node_tokens
    float* out2 = out1 + (size_t)N * 256;              // edge_tokens
    float* out3 = out2 + (size_t)E * 256;              // subgraph_tokens
    float* out4 = out3 + (size_t)N * 256;              // neighborhood_tokens

    float *pP, *pQ, *pNbr, *pF2, *pS1, *pT1;
    cudaGetSymbolAddress((void**)&pP,  g_P);
    cudaGetSymbolAddress((void**)&pQ,  g_Q);
    cudaGetSymbolAddress((void**)&pNbr, g_nbr);
    cudaGetSymbolAddress((void**)&pF2, g_f2);
    cudaGetSymbolAddress((void**)&pS1, g_S1);
    cudaGetSymbolAddress((void**)&pT1, g_T1);

    size_t f2_smem = (size_t)(F2_TR * 128) * sizeof(float) + (F2_MI * 6) * sizeof(unsigned);
    cudaFuncSetAttribute(feat2_kernel, cudaFuncAttributeMaxDynamicSharedMemorySize,
                         (int)f2_smem);

    dim3 gblk(256);
    int rt = (N + 127) / 128;

    // zero accumulating scratch
    zero_kernel<<<512, 256>>>(N, WORDS);

    // --- fused tokenizer GEMMs: out1 = x@Wn+bn, P = x@We_top+be, Q = x@We_bot ---
    {
        Job ja = {x, nullptr, nullptr, Wn, bn, out1, 1, 0};
        Job jb = {x, nullptr, nullptr, We, be, pP,   1, 0};
        Job jc = {x, nullptr, nullptr, We + (size_t)F * 256, nullptr, pQ, 1, 0};
        sgemm_kernel<<<dim3(2, rt, 3), gblk>>>(ja, jb, jc, N);
    }

    // graph structure
    int eb = (E + 255) / 256;
    edge_prep_kernel<<<eb, 256>>>(row, col, E, WORDS);
    scan_kernel<<<1, 1024>>>(N);
    scatter_kernel<<<eb, 256>>>(row, col, E);

    // 1-hop mean + 2-hop reach bitsets
    hop1_kernel<<<N, 256>>>(out1, N, WORDS);

    // edge tokens
    long long etot = (long long)E * 64;
    int etb = (int)((etot + 255) / 256);
    edge_tok_kernel<<<etb, 256>>>(row, col, out2, E);

    // feat2 (2-hop unique mean)
    int f2grid = (N + F2_MI - 1) / F2_MI;
    feat2_kernel<<<dim3(f2grid, 2), 256, f2_smem>>>(out1, N, WORDS);

    // --- fused MLP layer 1: S1 = relu([out1|nbr]@Ws1+bs1), T1 = relu([out1|nbr|f2]@Wh1+bh1) ---
    {
        Job ja = {out1, pNbr, nullptr, Ws1, bs1, pS1, 2, 1};
        Job jb = {out1, pNbr, pF2,     Wh1, bh1, pT1, 3, 1};
        sgemm_kernel<<<dim3(2, rt, 2), gblk>>>(ja, jb, ja, N);
    }

    // --- fused MLP layer 2: out3 = S1@Ws2+bs2, out4 = T1@Wh2+bh2 ---
    {
        Job ja = {pS1, nullptr, nullptr, Ws2, bs2, out3, 1, 0};
        Job jb = {pT1, nullptr, nullptr, Wh2, bh2, out4, 1, 0};
        sgemm_kernel<<<dim3(2, rt, 2), gblk>>>(ja, jb, ja, N);
    }
}